// round 4
// baseline (speedup 1.0000x reference)
#include <cuda_runtime.h>
#include <cstdint>
#include <math.h>

// Shape fixed by setup_inputs: B=2, H=16, S=2048, D=128, key block = 256
#define S_LEN 2048
#define D_DIM 128

#define SQ 64              // q rows per CTA
#define KSTR 132           // K tile stride: 132 % 32 == 4 -> QK B loads conflict-free
#define VSTR 136           // V tile stride: 136 % 32 == 8 -> PV B loads conflict-free
#define TILE_FLOATS (128 * VSTR)          // buffer sized for the larger stride
#define SMEM_FLOATS (2 * TILE_FLOATS + 256)
#define OSTR 130           // O-combine buffer stride

#define FULLM 0xffffffffu

__device__ __forceinline__ uint32_t tf32b(float x) {
    uint32_t u; asm("cvt.rna.tf32.f32 %0, %1;" : "=r"(u) : "f"(x)); return u;
}
__device__ __forceinline__ float tf32r(float x) { return __uint_as_float(tf32b(x)); }

// m16n8k8 tf32 HMMA, D += A*B
__device__ __forceinline__ void mma8(float* c, uint32_t a0, uint32_t a1,
                                     uint32_t a2, uint32_t a3,
                                     uint32_t b0, uint32_t b1) {
    asm volatile(
        "mma.sync.aligned.m16n8k8.row.col.f32.tf32.tf32.f32 "
        "{%0,%1,%2,%3}, {%4,%5,%6,%7}, {%8,%9}, {%0,%1,%2,%3};"
        : "+f"(c[0]), "+f"(c[1]), "+f"(c[2]), "+f"(c[3])
        : "r"(a0), "r"(a1), "r"(a2), "r"(a3), "r"(b0), "r"(b1));
}

// Stage a 128x128 f32 tile into smem with given stride, tf32-rna rounded.
template <int STRIDE>
__device__ __forceinline__ void stage_tile(float* dst, const float* __restrict__ src,
                                           int tid) {
    #pragma unroll
    for (int i = 0; i < 16; i++) {
        int idx = tid + 256 * i;
        int r = idx >> 5;
        int c4 = (idx & 31) << 2;
        float4 v = *(const float4*)(src + (size_t)r * D_DIM + c4);
        v.x = tf32r(v.x); v.y = tf32r(v.y); v.z = tf32r(v.z); v.w = tf32r(v.w);
        *(float4*)(dst + r * STRIDE + c4) = v;
    }
}

// ---------------------------------------------------------------------------
// Blocked attention, register-resident P.
// CTA: 64 q rows, 8 warps = 4(m: 16 rows) x 2(h: 128-key half).
// Per key block jb: warp (m,h) computes S tile 16x128 in regs, softmax with
// one cross-half smem exchange, SHFL-permute C-layout -> A-layout, PV
// accumulates normalized P into O fragments (held across jb). h-pairs of
// warps sum partial O once at the end.
// ---------------------------------------------------------------------------
__global__ __launch_bounds__(256, 1)
void attn_mma_kernel(const float* __restrict__ Q,
                     const float* __restrict__ K,
                     const float* __restrict__ V,
                     float* __restrict__ O) {
    extern __shared__ float sm[];
    float* t0 = sm;                        // tile buffer 0
    float* t1 = sm + TILE_FLOATS;          // tile buffer 1
    float* pmax = sm + 2 * TILE_FLOATS;    // [4m][2h][16rows]
    float* psum = pmax + 128;

    const int tid  = threadIdx.x;
    const int wid  = tid >> 5;
    const int lane = tid & 31;
    const int m = wid & 3;
    const int h = wid >> 2;
    const int g = lane >> 2;
    const int t = lane & 3;

    const int bh = blockIdx.y;
    const int qb = blockIdx.x;
    const size_t bhoff = (size_t)bh * S_LEN * D_DIM;
    const float* Qb = Q + bhoff + (size_t)qb * SQ * D_DIM;
    const float* Kb = K + bhoff;
    const float* Vb = V + bhoff;
    float* Ob = O + bhoff + (size_t)qb * SQ * D_DIM;

    // ---- Q A-fragments in regs: rows 16m+g(+8), cols 8ks+t(+4), tf32 ----
    uint32_t aq[16][4];
    {
        const float* q0 = Qb + (size_t)(16 * m + g) * D_DIM;
        const float* q1 = q0 + 8 * D_DIM;
        #pragma unroll
        for (int ks = 0; ks < 16; ks++) {
            int c = ks * 8 + t;
            aq[ks][0] = tf32b(q0[c]);
            aq[ks][1] = tf32b(q1[c]);
            aq[ks][2] = tf32b(q0[c + 4]);
            aq[ks][3] = tf32b(q1[c + 4]);
        }
    }

    // ---- O accumulators: 16 rows x 128 dims per warp (partial over h-keys) ----
    float oacc[16][4];
    #pragma unroll
    for (int nt = 0; nt < 16; nt++)
        #pragma unroll
        for (int j = 0; j < 4; j++) oacc[nt][j] = 0.0f;

    const float cexp = 0.08838834764831845f * 1.4426950408889634f; // D^-0.5*log2(e)
    const int srcA = (lane & ~3) | (t >> 1);
    const int srcB = srcA + 2;
    const bool odd = (t & 1) != 0;
    const int pb_mine  = (m * 2 + h) * 16 + g;
    const int pb_other = (m * 2 + (1 - h)) * 16 + g;

    for (int jb = 0; jb < S_LEN / 256; jb++) {
        // ================= stage K (two 128-key tiles, stride 132) ============
        stage_tile<KSTR>(t0, Kb + (size_t)(jb * 256) * D_DIM, tid);
        stage_tile<KSTR>(t1, Kb + (size_t)(jb * 256 + 128) * D_DIM, tid);
        __syncthreads();

        // ================= QK^T: 16x128 per warp, keys of half h ==============
        float c[16][4];
        #pragma unroll
        for (int nt = 0; nt < 16; nt++)
            #pragma unroll
            for (int j = 0; j < 4; j++) c[nt][j] = 0.0f;
        {
            const float* kh = h ? t1 : t0;
            #pragma unroll 4
            for (int ks = 0; ks < 16; ks++) {
                const float* kc = kh + ks * 8 + t;
                #pragma unroll
                for (int nt = 0; nt < 16; nt++) {
                    const float* kp = kc + (nt * 8 + g) * KSTR;
                    mma8(c[nt], aq[ks][0], aq[ks][1], aq[ks][2], aq[ks][3],
                         __float_as_uint(kp[0]), __float_as_uint(kp[4]));
                }
            }
        }

        // ================= softmax in regs (local half) =======================
        float m0 = -INFINITY, m1 = -INFINITY;
        #pragma unroll
        for (int nt = 0; nt < 16; nt++) {
            m0 = fmaxf(m0, fmaxf(c[nt][0], c[nt][1]));
            m1 = fmaxf(m1, fmaxf(c[nt][2], c[nt][3]));
        }
        m0 = fmaxf(m0, __shfl_xor_sync(FULLM, m0, 1));
        m0 = fmaxf(m0, __shfl_xor_sync(FULLM, m0, 2));
        m1 = fmaxf(m1, __shfl_xor_sync(FULLM, m1, 1));
        m1 = fmaxf(m1, __shfl_xor_sync(FULLM, m1, 2));

        float s0 = 0.0f, s1 = 0.0f;
        #pragma unroll
        for (int nt = 0; nt < 16; nt++) {
            c[nt][0] = exp2f((c[nt][0] - m0) * cexp); s0 += c[nt][0];
            c[nt][1] = exp2f((c[nt][1] - m0) * cexp); s0 += c[nt][1];
            c[nt][2] = exp2f((c[nt][2] - m1) * cexp); s1 += c[nt][2];
            c[nt][3] = exp2f((c[nt][3] - m1) * cexp); s1 += c[nt][3];
        }
        s0 += __shfl_xor_sync(FULLM, s0, 1);
        s0 += __shfl_xor_sync(FULLM, s0, 2);
        s1 += __shfl_xor_sync(FULLM, s1, 1);
        s1 += __shfl_xor_sync(FULLM, s1, 2);

        if (t == 0) {
            pmax[pb_mine] = m0;  pmax[pb_mine + 8] = m1;
            psum[pb_mine] = s0;  psum[pb_mine + 8] = s1;
        }
        __syncthreads();
        float scale0, scale1;
        {
            float M0o = pmax[pb_other], M1o = pmax[pb_other + 8];
            float S0o = psum[pb_other], S1o = psum[pb_other + 8];
            float M0 = fmaxf(m0, M0o);
            float M1 = fmaxf(m1, M1o);
            float cr0 = exp2f((m0 - M0) * cexp);
            float cr1 = exp2f((m1 - M1) * cexp);
            float S0 = s0 * cr0 + S0o * exp2f((M0o - M0) * cexp);
            float S1 = s1 * cr1 + S1o * exp2f((M1o - M1) * cexp);
            scale0 = cr0 / S0;
            scale1 = cr1 / S1;
        }

        // ================= stage V (issue LDGs before shuffle work) ===========
        stage_tile<VSTR>(t0, Vb + (size_t)(jb * 256) * D_DIM, tid);
        stage_tile<VSTR>(t1, Vb + (size_t)(jb * 256 + 128) * D_DIM, tid);

        // ===== permute P: C-layout (2t,2t+1) -> A-layout (t,t+4), tf32 ========
        #pragma unroll
        for (int nt = 0; nt < 16; nt++) {
            float x0 = c[nt][0] * scale0, x1 = c[nt][1] * scale0;
            float x2 = c[nt][2] * scale1, x3 = c[nt][3] * scale1;
            float e0 = __shfl_sync(FULLM, x0, srcA), e1 = __shfl_sync(FULLM, x1, srcA);
            float f0 = __shfl_sync(FULLM, x0, srcB), f1 = __shfl_sync(FULLM, x1, srcB);
            float u0 = __shfl_sync(FULLM, x2, srcA), u1 = __shfl_sync(FULLM, x3, srcA);
            float v0 = __shfl_sync(FULLM, x2, srcB), v1 = __shfl_sync(FULLM, x3, srcB);
            c[nt][0] = tf32r(odd ? e1 : e0);   // a0: (r0, t)
            c[nt][1] = tf32r(odd ? u1 : u0);   // a1: (r1, t)
            c[nt][2] = tf32r(odd ? f1 : f0);   // a2: (r0, t+4)
            c[nt][3] = tf32r(odd ? v1 : v0);   // a3: (r1, t+4)
        }
        __syncthreads();   // V tiles ready

        // ================= PV: O(16x128) += P V over this warp's 128 keys =====
        {
            const float* vh = h ? t1 : t0;
            #pragma unroll 4
            for (int ks = 0; ks < 16; ks++) {
                const float* vr = vh + (ks * 8 + t) * VSTR + g;
                uint32_t A0 = __float_as_uint(c[ks][0]);
                uint32_t A1 = __float_as_uint(c[ks][1]);
                uint32_t A2 = __float_as_uint(c[ks][2]);
                uint32_t A3 = __float_as_uint(c[ks][3]);
                #pragma unroll
                for (int nt = 0; nt < 16; nt++) {
                    mma8(oacc[nt], A0, A1, A2, A3,
                         __float_as_uint(vr[nt * 8]),
                         __float_as_uint(vr[nt * 8 + 4 * VSTR]));
                }
            }
        }
        __syncthreads();   // protect tiles + pbuf for next jb
    }

    // ================= combine h-halves, write O ==============================
    if (h == 1) {
        float* ob0 = t0 + (m * 16 + g) * OSTR + 2 * t;
        float* ob1 = t0 + (m * 16 + g + 8) * OSTR + 2 * t;
        #pragma unroll
        for (int nt = 0; nt < 16; nt++) {
            *(float2*)(ob0 + nt * 8) = make_float2(oacc[nt][0], oacc[nt][1]);
            *(float2*)(ob1 + nt * 8) = make_float2(oacc[nt][2], oacc[nt][3]);
        }
    }
    __syncthreads();
    if (h == 0) {
        const float* ob0 = t0 + (m * 16 + g) * OSTR + 2 * t;
        const float* ob1 = t0 + (m * 16 + g + 8) * OSTR + 2 * t;
        float* o0 = Ob + (size_t)(16 * m + g) * D_DIM + 2 * t;
        float* o1 = o0 + 8 * D_DIM;
        #pragma unroll
        for (int nt = 0; nt < 16; nt++) {
            float2 p0 = *(const float2*)(ob0 + nt * 8);
            float2 p1 = *(const float2*)(ob1 + nt * 8);
            *(float2*)(o0 + nt * 8) = make_float2(oacc[nt][0] + p0.x, oacc[nt][1] + p0.y);
            *(float2*)(o1 + nt * 8) = make_float2(oacc[nt][2] + p1.x, oacc[nt][3] + p1.y);
        }
    }
}

// ---------------------------------------------------------------------------
extern "C" void kernel_launch(void* const* d_in, const int* in_sizes, int n_in,
                              void* d_out, int out_size) {
    const float* Q = (const float*)d_in[0];
    const float* K = (const float*)d_in[1];
    const float* V = (const float*)d_in[2];
    float* O = (float*)d_out;

    const int bh = in_sizes[0] / (S_LEN * D_DIM);   // 32

    const size_t smem_bytes = (size_t)SMEM_FLOATS * sizeof(float);
    cudaFuncSetAttribute(attn_mma_kernel, cudaFuncAttributeMaxDynamicSharedMemorySize,
                         (int)smem_bytes);
    attn_mma_kernel<<<dim3(S_LEN / SQ, bh), 256, smem_bytes>>>(Q, K, V, O);
}

// round 5
// speedup vs baseline: 1.1416x; 1.1416x over previous
#include <cuda_runtime.h>
#include <cstdint>
#include <math.h>

// Shape fixed by setup_inputs: B=2, H=16, S=2048, D=128, key block = 256
#define S_LEN 2048
#define D_DIM 128

#define NT 512             // 16 warps = 4 m-groups x 4 key-groups
#define QSTR 132           // Q tile stride (132%32==4 -> conflict-free A loads)
#define KSTR 132           // K tile stride (QK B loads conflict-free: 4g+t)
#define VSTR 136           // V tile stride (PV B loads conflict-free: 8t+g)
#define OSTR 132           // O partial-combine stride
#define Q_FLOATS (64 * QSTR)                 // 8448
#define TILE_FLOATS (128 * VSTR)             // 17408 (sized for larger stride)
#define PBUF_OFF (Q_FLOATS + 2 * TILE_FLOATS)
#define SMEM_FLOATS (PBUF_OFF + 512)         // + pmax[256], psum[256]

#define FULLM 0xffffffffu

__device__ __forceinline__ uint32_t tf32b(float x) {
    uint32_t u; asm("cvt.rna.tf32.f32 %0, %1;" : "=r"(u) : "f"(x)); return u;
}
__device__ __forceinline__ float tf32r(float x) { return __uint_as_float(tf32b(x)); }

// m16n8k8 tf32 HMMA, D += A*B
__device__ __forceinline__ void mma8(float* c, uint32_t a0, uint32_t a1,
                                     uint32_t a2, uint32_t a3,
                                     uint32_t b0, uint32_t b1) {
    asm volatile(
        "mma.sync.aligned.m16n8k8.row.col.f32.tf32.tf32.f32 "
        "{%0,%1,%2,%3}, {%4,%5,%6,%7}, {%8,%9}, {%0,%1,%2,%3};"
        : "+f"(c[0]), "+f"(c[1]), "+f"(c[2]), "+f"(c[3])
        : "r"(a0), "r"(a1), "r"(a2), "r"(a3), "r"(b0), "r"(b1));
}

// Stage a 128x128 f32 tile into smem (given stride), tf32-rna rounded. NT threads.
template <int STRIDE>
__device__ __forceinline__ void stage_tile(float* dst, const float* __restrict__ src,
                                           int tid) {
    #pragma unroll
    for (int i = 0; i < 4096 / NT; i++) {
        int idx = tid + NT * i;
        int r = idx >> 5;
        int c4 = (idx & 31) << 2;
        float4 v = *(const float4*)(src + (size_t)r * D_DIM + c4);
        v.x = tf32r(v.x); v.y = tf32r(v.y); v.z = tf32r(v.z); v.w = tf32r(v.w);
        *(float4*)(dst + r * STRIDE + c4) = v;
    }
}

// ---------------------------------------------------------------------------
// Blocked attention. CTA: 64 q rows, 16 warps = 4(m: 16 rows) x 4(kg: 64 keys).
// Per key block jb (256 keys): warp computes its 16x64 score tile in regs
// (Q A-frags streamed from smem), 4-way cross-kg softmax merge via smem,
// SHFL-permute to A-layout, PV accumulates into 16x128 O fragments held
// across jb; 4-way O combine at the end.
// ---------------------------------------------------------------------------
__global__ __launch_bounds__(NT, 1)
void attn_mma_kernel(const float* __restrict__ Q,
                     const float* __restrict__ K,
                     const float* __restrict__ V,
                     float* __restrict__ O) {
    extern __shared__ float sm[];
    float* qs = sm;                        // Q tile [64][QSTR]
    float* t0 = sm + Q_FLOATS;             // K/V tile 0 (keys 0-127)
    float* t1 = t0 + TILE_FLOATS;          // K/V tile 1 (keys 128-255)
    float* pmax = sm + PBUF_OFF;           // [4kg][64 rows]
    float* psum = pmax + 256;

    const int tid  = threadIdx.x;
    const int wid  = tid >> 5;
    const int lane = tid & 31;
    const int m  = wid & 3;                // row group: rows 16m..16m+15
    const int kg = wid >> 2;               // key group: keys 64kg..64kg+63
    const int g = lane >> 2;
    const int t = lane & 3;

    const int bh = blockIdx.y;
    const int qb = blockIdx.x;
    const size_t bhoff = (size_t)bh * S_LEN * D_DIM;
    const float* Qb = Q + bhoff + (size_t)qb * 64 * D_DIM;
    const float* Kb = K + bhoff;
    const float* Vb = V + bhoff;
    float* Ob = O + bhoff + (size_t)qb * 64 * D_DIM;

    // ---- stage Q once ----
    #pragma unroll
    for (int i = 0; i < 2048 / NT; i++) {
        int idx = tid + NT * i;
        int r = idx >> 5;
        int c4 = (idx & 31) << 2;
        float4 v = *(const float4*)(Qb + (size_t)r * D_DIM + c4);
        v.x = tf32r(v.x); v.y = tf32r(v.y); v.z = tf32r(v.z); v.w = tf32r(v.w);
        *(float4*)(qs + r * QSTR + c4) = v;
    }

    // ---- O accumulators: 16 rows x 128 d per warp (partial over kg keys) ----
    float oacc[16][4];
    #pragma unroll
    for (int dt = 0; dt < 16; dt++)
        #pragma unroll
        for (int j = 0; j < 4; j++) oacc[dt][j] = 0.0f;

    const float cexp = 0.08838834764831845f * 1.4426950408889634f; // D^-0.5*log2(e)
    const int srcA = (lane & ~3) | (t >> 1);
    const int srcB = srcA + 2;
    const bool odd = (t & 1) != 0;
    const int row0 = 16 * m + g;           // first of the lane's two rows
    const float* a0p = qs + row0 * QSTR + t;
    const float* a1p = a0p + 8 * QSTR;
    // this warp's key tile base (within t0/t1), same offsets valid for K and V strides
    float* const ktile = (kg < 2 ? t0 : t1);
    const int koff = (kg & 1) * 64;

    __syncthreads();   // Q staged (also guards pbuf init races: none yet)

    for (int jb = 0; jb < S_LEN / 256; jb++) {
        // ================= stage K (keys 0-127 -> t0, 128-255 -> t1) =========
        stage_tile<KSTR>(t0, Kb + (size_t)(jb * 256) * D_DIM, tid);
        stage_tile<KSTR>(t1, Kb + (size_t)(jb * 256 + 128) * D_DIM, tid);
        __syncthreads();

        // ================= QK^T: 16 rows x 64 keys per warp ===================
        float c[8][4];
        #pragma unroll
        for (int nt = 0; nt < 8; nt++)
            #pragma unroll
            for (int j = 0; j < 4; j++) c[nt][j] = 0.0f;
        {
            const float* kb = ktile + koff * KSTR;
            #pragma unroll 4
            for (int ks = 0; ks < 16; ks++) {
                uint32_t A0 = __float_as_uint(a0p[ks * 8]);
                uint32_t A1 = __float_as_uint(a1p[ks * 8]);
                uint32_t A2 = __float_as_uint(a0p[ks * 8 + 4]);
                uint32_t A3 = __float_as_uint(a1p[ks * 8 + 4]);
                const float* kc = kb + ks * 8 + t;
                #pragma unroll
                for (int nt = 0; nt < 8; nt++) {
                    const float* kp = kc + (nt * 8 + g) * KSTR;
                    mma8(c[nt], A0, A1, A2, A3,
                         __float_as_uint(kp[0]), __float_as_uint(kp[4]));
                }
            }
        }

        // ================= softmax: local over 64 keys ========================
        float m0 = -INFINITY, m1 = -INFINITY;
        #pragma unroll
        for (int nt = 0; nt < 8; nt++) {
            m0 = fmaxf(m0, fmaxf(c[nt][0], c[nt][1]));
            m1 = fmaxf(m1, fmaxf(c[nt][2], c[nt][3]));
        }
        m0 = fmaxf(m0, __shfl_xor_sync(FULLM, m0, 1));
        m0 = fmaxf(m0, __shfl_xor_sync(FULLM, m0, 2));
        m1 = fmaxf(m1, __shfl_xor_sync(FULLM, m1, 1));
        m1 = fmaxf(m1, __shfl_xor_sync(FULLM, m1, 2));

        float s0 = 0.0f, s1 = 0.0f;
        #pragma unroll
        for (int nt = 0; nt < 8; nt++) {
            c[nt][0] = exp2f((c[nt][0] - m0) * cexp); s0 += c[nt][0];
            c[nt][1] = exp2f((c[nt][1] - m0) * cexp); s0 += c[nt][1];
            c[nt][2] = exp2f((c[nt][2] - m1) * cexp); s1 += c[nt][2];
            c[nt][3] = exp2f((c[nt][3] - m1) * cexp); s1 += c[nt][3];
        }
        s0 += __shfl_xor_sync(FULLM, s0, 1);
        s0 += __shfl_xor_sync(FULLM, s0, 2);
        s1 += __shfl_xor_sync(FULLM, s1, 1);
        s1 += __shfl_xor_sync(FULLM, s1, 2);

        if (t == 0) {
            pmax[kg * 64 + row0] = m0;  pmax[kg * 64 + row0 + 8] = m1;
            psum[kg * 64 + row0] = s0;  psum[kg * 64 + row0 + 8] = s1;
        }
        __syncthreads();   // QK reads done + partials visible

        // ---- 4-way merge -> per-row scale for this kg ----
        float scale0, scale1;
        {
            float M0 = -INFINITY, M1 = -INFINITY;
            #pragma unroll
            for (int j = 0; j < 4; j++) {
                M0 = fmaxf(M0, pmax[j * 64 + row0]);
                M1 = fmaxf(M1, pmax[j * 64 + row0 + 8]);
            }
            float S0 = 0.0f, S1 = 0.0f;
            #pragma unroll
            for (int j = 0; j < 4; j++) {
                S0 += psum[j * 64 + row0]     * exp2f((pmax[j * 64 + row0]     - M0) * cexp);
                S1 += psum[j * 64 + row0 + 8] * exp2f((pmax[j * 64 + row0 + 8] - M1) * cexp);
            }
            scale0 = exp2f((m0 - M0) * cexp) / S0;
            scale1 = exp2f((m1 - M1) * cexp) / S1;
        }

        // ================= stage V (overwrites K tiles) =======================
        stage_tile<VSTR>(t0, Vb + (size_t)(jb * 256) * D_DIM, tid);
        stage_tile<VSTR>(t1, Vb + (size_t)(jb * 256 + 128) * D_DIM, tid);

        // ===== permute P: C-layout (2t,2t+1) -> A-layout (t,t+4), tf32 ========
        #pragma unroll
        for (int nt = 0; nt < 8; nt++) {
            float x0 = c[nt][0] * scale0, x1 = c[nt][1] * scale0;
            float x2 = c[nt][2] * scale1, x3 = c[nt][3] * scale1;
            float e0 = __shfl_sync(FULLM, x0, srcA), e1 = __shfl_sync(FULLM, x1, srcA);
            float f0 = __shfl_sync(FULLM, x0, srcB), f1 = __shfl_sync(FULLM, x1, srcB);
            float u0 = __shfl_sync(FULLM, x2, srcA), u1 = __shfl_sync(FULLM, x3, srcA);
            float v0 = __shfl_sync(FULLM, x2, srcB), v1 = __shfl_sync(FULLM, x3, srcB);
            c[nt][0] = tf32r(odd ? e1 : e0);
            c[nt][1] = tf32r(odd ? u1 : u0);
            c[nt][2] = tf32r(odd ? f1 : f0);
            c[nt][3] = tf32r(odd ? v1 : v0);
        }
        __syncthreads();   // V tiles ready

        // ================= PV: O(16x128) += P(16x64) V(64x128) ================
        {
            const float* vb = ktile + koff * VSTR;
            #pragma unroll 2
            for (int kc = 0; kc < 8; kc++) {
                const float* vr = vb + (kc * 8 + t) * VSTR + g;
                uint32_t A0 = __float_as_uint(c[kc][0]);
                uint32_t A1 = __float_as_uint(c[kc][1]);
                uint32_t A2 = __float_as_uint(c[kc][2]);
                uint32_t A3 = __float_as_uint(c[kc][3]);
                #pragma unroll
                for (int dt = 0; dt < 16; dt++) {
                    mma8(oacc[dt], A0, A1, A2, A3,
                         __float_as_uint(vr[dt * 8]),
                         __float_as_uint(vr[dt * 8 + 4 * VSTR]));
                }
            }
        }
        __syncthreads();   // V reads done before next jb restage
    }

    // ================= combine 4 kg partials, write O =========================
    // kg 1..3 store partials into smem (reuse Q + tile area), kg 0 sums.
    float* obuf = sm;   // 3 * 64 * OSTR floats = 25344 < SMEM_FLOATS
    if (kg != 0) {
        float* p0 = obuf + ((kg - 1) * 64 + row0) * OSTR + 2 * t;
        float* p1 = p0 + 8 * OSTR;
        #pragma unroll
        for (int dt = 0; dt < 16; dt++) {
            *(float2*)(p0 + dt * 8) = make_float2(oacc[dt][0], oacc[dt][1]);
            *(float2*)(p1 + dt * 8) = make_float2(oacc[dt][2], oacc[dt][3]);
        }
    }
    __syncthreads();
    if (kg == 0) {
        float* o0 = Ob + (size_t)row0 * D_DIM + 2 * t;
        float* o1 = o0 + 8 * D_DIM;
        const float* p0 = obuf + row0 * OSTR + 2 * t;
        const float* p1 = p0 + 8 * OSTR;
        #pragma unroll
        for (int dt = 0; dt < 16; dt++) {
            float a0 = oacc[dt][0], a1 = oacc[dt][1];
            float a2 = oacc[dt][2], a3 = oacc[dt][3];
            #pragma unroll
            for (int j = 0; j < 3; j++) {
                float2 q0 = *(const float2*)(p0 + j * 64 * OSTR + dt * 8);
                float2 q1 = *(const float2*)(p1 + j * 64 * OSTR + dt * 8);
                a0 += q0.x; a1 += q0.y; a2 += q1.x; a3 += q1.y;
            }
            *(float2*)(o0 + dt * 8) = make_float2(a0, a1);
            *(float2*)(o1 + dt * 8) = make_float2(a2, a3);
        }
    }
}

// ---------------------------------------------------------------------------
extern "C" void kernel_launch(void* const* d_in, const int* in_sizes, int n_in,
                              void* d_out, int out_size) {
    const float* Q = (const float*)d_in[0];
    const float* K = (const float*)d_in[1];
    const float* V = (const float*)d_in[2];
    float* O = (float*)d_out;

    const int bh = in_sizes[0] / (S_LEN * D_DIM);   // 32

    const size_t smem_bytes = (size_t)SMEM_FLOATS * sizeof(float);
    cudaFuncSetAttribute(attn_mma_kernel, cudaFuncAttributeMaxDynamicSharedMemorySize,
                         (int)smem_bytes);
    attn_mma_kernel<<<dim3(S_LEN / 64, bh), NT, smem_bytes>>>(Q, K, V, O);
}

// round 7
// speedup vs baseline: 1.2439x; 1.0896x over previous
#include <cuda_runtime.h>
#include <cstdint>
#include <math.h>

// Shape fixed by setup_inputs: B=2, H=16, S=2048, D=128, key block = 256
#define S_LEN 2048
#define D_DIM 128
#define BH 32
#define NT 512
#define FULLM 0xffffffffu

// smem layout (floats)
#define QSTR 132
#define Q_FLOATS (64 * QSTR)                       // 8448
#define SLOT_FLOATS (64 * 128)                     // 8192 (64 keys x 128 d, no pad)
#define NSLOT 5
#define SLOTS_OFF Q_FLOATS
#define PBUF_OFF (SLOTS_OFF + NSLOT * SLOT_FLOATS) // pmax[2][256], psum[2][256]
#define MBAR_OFF (PBUF_OFF + 1024)                 // 10 x u64 barriers
#define SMEM_FLOATS (MBAR_OFF + 64)
#define OSTR 132

// tf32-prerounded K/V scratch
__device__ float g_Kr[(size_t)BH * S_LEN * D_DIM];
__device__ float g_Vr[(size_t)BH * S_LEN * D_DIM];

__device__ __forceinline__ uint32_t tf32b(float x) {
    uint32_t u; asm("cvt.rna.tf32.f32 %0, %1;" : "=r"(u) : "f"(x)); return u;
}
__device__ __forceinline__ float tf32r(float x) { return __uint_as_float(tf32b(x)); }

__device__ __forceinline__ uint32_t smem_u32(const void* p) {
    uint32_t a;
    asm("{ .reg .u64 t; cvta.to.shared.u64 t, %1; cvt.u32.u64 %0, t; }" : "=r"(a) : "l"(p));
    return a;
}

#define MB_INIT(mb, c) asm volatile("mbarrier.init.shared.b64 [%0], %1;" :: "r"(mb), "r"(c) : "memory")
#define MB_ARRIVE(mb)  asm volatile("mbarrier.arrive.shared.b64 _, [%0];" :: "r"(mb) : "memory")
#define CP16(dst, src) asm volatile("cp.async.cg.shared.global [%0], [%1], 16;" :: "r"(dst), "l"(src) : "memory")
// NOTE: .noinc is load-bearing. Without it the arrive first increments the
// pending count (net zero) and the barrier never completes -> R6 hang.
#define CP_ARRIVE(mb)  asm volatile("cp.async.mbarrier.arrive.noinc.shared.b64 [%0];" :: "r"(mb) : "memory")

#define MB_WAIT(mbar_addr, phase) do {                                             \
    uint32_t _mb = (mbar_addr); uint32_t _ph = (phase); uint32_t _done;            \
    asm volatile("{ .reg .pred p; mbarrier.try_wait.parity.acquire.cta.shared::cta.b64 p, [%1], %2; selp.b32 %0, 1, 0, p; }" \
        : "=r"(_done) : "r"(_mb), "r"(_ph) : "memory");                            \
    if (!_done) {                                                                  \
        asm volatile("{ .reg .pred P1; WL_%=: mbarrier.try_wait.parity.acquire.cta.shared::cta.b64 P1, [%0], %1, 0x989680; @P1 bra.uni WD_%=; bra.uni WL_%=; WD_%=: }" \
            :: "r"(_mb), "r"(_ph) : "memory");                                     \
    }                                                                              \
} while (0)

// m16n8k8 tf32 HMMA, D += A*B
__device__ __forceinline__ void mma8(float* c, uint32_t a0, uint32_t a1,
                                     uint32_t a2, uint32_t a3,
                                     uint32_t b0, uint32_t b1) {
    asm volatile(
        "mma.sync.aligned.m16n8k8.row.col.f32.tf32.tf32.f32 "
        "{%0,%1,%2,%3}, {%4,%5,%6,%7}, {%8,%9}, {%0,%1,%2,%3};"
        : "+f"(c[0]), "+f"(c[1]), "+f"(c[2]), "+f"(c[3])
        : "r"(a0), "r"(a1), "r"(a2), "r"(a3), "r"(b0), "r"(b1));
}

// ---------------------------------------------------------------------------
// Pre-pass: round K, V to tf32 (rna) into scratch.
// ---------------------------------------------------------------------------
__global__ void round_kernel(const float* __restrict__ K, const float* __restrict__ V) {
    size_t i = (size_t)blockIdx.x * 256 + threadIdx.x;
    const float4* s = (const float4*)(blockIdx.y ? V : K);
    float4* d = (float4*)(blockIdx.y ? g_Vr : g_Kr);
    float4 v = s[i];
    v.x = tf32r(v.x); v.y = tf32r(v.y); v.z = tf32r(v.z); v.w = tf32r(v.w);
    d[i] = v;
}

// ---------------------------------------------------------------------------
// Main kernel. CTA: 64 q rows, 16 warps = 4(m) x 4(kg: 64 keys).
// Chunk ring: per jb 8 chunks (K0-3,V0-3), 64 keys x 128 d each, XOR-swizzled,
// produced via cp.async by all threads, consumed by one kg-group each.
// ---------------------------------------------------------------------------
__global__ __launch_bounds__(NT, 1)
void attn_mma_kernel(const float* __restrict__ Q, float* __restrict__ O) {
    extern __shared__ float smf[];
    const uint32_t sbase = smem_u32(smf);
    const uint32_t slots_sa = sbase + SLOTS_OFF * 4;
    const uint32_t mb_full  = sbase + MBAR_OFF * 4;        // 5 x u64
    const uint32_t mb_empty = mb_full + NSLOT * 8;         // 5 x u64
    float* qs = smf;
    float* pmax = smf + PBUF_OFF;                          // [2][256]
    float* psum = pmax + 512;

    const int tid  = threadIdx.x;
    const int wid  = tid >> 5;
    const int lane = tid & 31;
    const int m  = wid & 3;
    const int kg = wid >> 2;
    const int g = lane >> 2;
    const int t = lane & 3;
    const int g3 = g & 3;
    const int g24 = (g >> 2) << 2;     // 4*(g>>2)

    const int bh = blockIdx.y;
    const int qb = blockIdx.x;
    const size_t bhoff = (size_t)bh * S_LEN * D_DIM;
    const float* Qb = Q + bhoff + (size_t)qb * 64 * D_DIM;
    const float* Krb = g_Kr + bhoff;
    const float* Vrb = g_Vr + bhoff;
    float* Ob = O + bhoff + (size_t)qb * 64 * D_DIM;

    // ---- init barriers ----
    if (tid == 0) {
        #pragma unroll
        for (int s = 0; s < NSLOT; s++) {
            MB_INIT(mb_full + s * 8, NT);     // one cp-arrive per thread
            MB_INIT(mb_empty + s * 8, 128);   // 4 consumer warps
        }
    }
    __syncthreads();

    // ---- producer lambda: stage chunk n (if n < 64) ----
    auto produce = [&](int n) {
        if (n >= 64) return;
        int q5 = n / 5;
        int slot = n - q5 * 5;
        uint32_t db = slots_sa + (uint32_t)slot * (SLOT_FLOATS * 4);
        if (n >= 5) MB_WAIT(mb_empty + slot * 8, (q5 - 1) & 1);
        int r = n & 7;
        const float* src = ((r < 4) ? Krb : Vrb)
                         + ((size_t)((n >> 3) * 256 + (r & 3) * 64)) * D_DIM;
        #pragma unroll
        for (int i = 0; i < 4; i++) {
            int u = tid + NT * i;           // 0..2047
            int row = u >> 5;               // 0..63
            int c16 = u & 31;
            int r3 = row & 7;
            int f = ((r3 & 3) << 1) | (r3 >> 2);
            uint32_t dst = db + (uint32_t)row * 512 + (uint32_t)((c16 ^ f) << 4);
            CP16(dst, src + row * D_DIM + c16 * 4);
        }
        CP_ARRIVE(mb_full + slot * 8);
    };

    // ---- stage Q (tf32, stride 132) ----
    #pragma unroll
    for (int i = 0; i < 2048 / NT; i++) {
        int idx = tid + NT * i;
        int r = idx >> 5;
        int c4 = (idx & 31) << 2;
        float4 v = *(const float4*)(Qb + (size_t)r * D_DIM + c4);
        v.x = tf32r(v.x); v.y = tf32r(v.y); v.z = tf32r(v.z); v.w = tf32r(v.w);
        *(float4*)(qs + r * QSTR + c4) = v;
    }

    // prologue: fill the ring
    produce(0); produce(1); produce(2); produce(3); produce(4);

    float oacc[16][4];
    #pragma unroll
    for (int dt = 0; dt < 16; dt++)
        #pragma unroll
        for (int j = 0; j < 4; j++) oacc[dt][j] = 0.0f;

    const float cexp = 0.08838834764831845f * 1.4426950408889634f; // D^-0.5*log2(e)
    const int srcA = (lane & ~3) | (t >> 1);
    const int srcB = srcA + 2;
    const bool odd = (t & 1) != 0;
    const int row0 = 16 * m + g;
    const float* a0p = qs + row0 * QSTR + t;
    const float* a1p = a0p + 8 * QSTR;

    __syncthreads();   // Q visible (and barrier init for everyone)

    #pragma unroll 1
    for (int jb = 0; jb < 8; jb++) {
        const int base = jb * 8;

        // ================= QK consume: chunk base+kg =========================
        const int nk = base + kg;
        const int qk5 = nk / 5, sk = nk - qk5 * 5;
        MB_WAIT(mb_full + sk * 8, qk5 & 1);
        const float* kb = smf + SLOTS_OFF + sk * SLOT_FLOATS;

        float c[8][4];
        #pragma unroll
        for (int nt = 0; nt < 8; nt++)
            #pragma unroll
            for (int j = 0; j < 4; j++) c[nt][j] = 0.0f;

        #pragma unroll 4
        for (int ks = 0; ks < 16; ks++) {
            uint32_t A0 = __float_as_uint(a0p[ks * 8]);
            uint32_t A1 = __float_as_uint(a1p[ks * 8]);
            uint32_t A2 = __float_as_uint(a0p[ks * 8 + 4]);
            uint32_t A3 = __float_as_uint(a1p[ks * 8 + 4]);
            const int off0 = ((ks ^ g3) << 3) + g24 + t;
            const int off1 = off0 ^ 4;
            #pragma unroll
            for (int nt = 0; nt < 8; nt++) {
                const float* kp = kb + (nt * 8 + g) * 128;
                mma8(c[nt], A0, A1, A2, A3,
                     __float_as_uint(kp[off0]), __float_as_uint(kp[off1]));
            }
        }
        MB_ARRIVE(mb_empty + sk * 8);

        // overlap: stage this jb's V1..V3
        produce(base + 5); produce(base + 6); produce(base + 7);

        // ================= softmax (local 64 keys) ============================
        float m0 = -INFINITY, m1 = -INFINITY;
        #pragma unroll
        for (int nt = 0; nt < 8; nt++) {
            m0 = fmaxf(m0, fmaxf(c[nt][0], c[nt][1]));
            m1 = fmaxf(m1, fmaxf(c[nt][2], c[nt][3]));
        }
        m0 = fmaxf(m0, __shfl_xor_sync(FULLM, m0, 1));
        m0 = fmaxf(m0, __shfl_xor_sync(FULLM, m0, 2));
        m1 = fmaxf(m1, __shfl_xor_sync(FULLM, m1, 1));
        m1 = fmaxf(m1, __shfl_xor_sync(FULLM, m1, 2));

        float s0 = 0.0f, s1 = 0.0f;
        #pragma unroll
        for (int nt = 0; nt < 8; nt++) {
            c[nt][0] = exp2f((c[nt][0] - m0) * cexp); s0 += c[nt][0];
            c[nt][1] = exp2f((c[nt][1] - m0) * cexp); s0 += c[nt][1];
            c[nt][2] = exp2f((c[nt][2] - m1) * cexp); s1 += c[nt][2];
            c[nt][3] = exp2f((c[nt][3] - m1) * cexp); s1 += c[nt][3];
        }
        s0 += __shfl_xor_sync(FULLM, s0, 1);
        s0 += __shfl_xor_sync(FULLM, s0, 2);
        s1 += __shfl_xor_sync(FULLM, s1, 1);
        s1 += __shfl_xor_sync(FULLM, s1, 2);

        float* pmx = pmax + (jb & 1) * 256;
        float* psm = psum + (jb & 1) * 256;
        if (t == 0) {
            pmx[kg * 64 + row0] = m0;  pmx[kg * 64 + row0 + 8] = m1;
            psm[kg * 64 + row0] = s0;  psm[kg * 64 + row0 + 8] = s1;
        }
        __syncthreads();

        float scale0, scale1;
        {
            float M0 = -INFINITY, M1 = -INFINITY;
            #pragma unroll
            for (int j = 0; j < 4; j++) {
                M0 = fmaxf(M0, pmx[j * 64 + row0]);
                M1 = fmaxf(M1, pmx[j * 64 + row0 + 8]);
            }
            float S0 = 0.0f, S1 = 0.0f;
            #pragma unroll
            for (int j = 0; j < 4; j++) {
                S0 += psm[j * 64 + row0]     * exp2f((pmx[j * 64 + row0]     - M0) * cexp);
                S1 += psm[j * 64 + row0 + 8] * exp2f((pmx[j * 64 + row0 + 8] - M1) * cexp);
            }
            scale0 = exp2f((m0 - M0) * cexp) / S0;
            scale1 = exp2f((m1 - M1) * cexp) / S1;
        }

        // next-jb K0 can be staged now (chunk base+3 consumers done pre-sync)
        produce(base + 8);

        // ===== permute P: C-layout (2t,2t+1) -> A-layout (t,t+4), tf32 ========
        #pragma unroll
        for (int nt = 0; nt < 8; nt++) {
            float x0 = c[nt][0] * scale0, x1 = c[nt][1] * scale0;
            float x2 = c[nt][2] * scale1, x3 = c[nt][3] * scale1;
            float e0 = __shfl_sync(FULLM, x0, srcA), e1 = __shfl_sync(FULLM, x1, srcA);
            float f0 = __shfl_sync(FULLM, x0, srcB), f1 = __shfl_sync(FULLM, x1, srcB);
            float u0 = __shfl_sync(FULLM, x2, srcA), u1 = __shfl_sync(FULLM, x3, srcA);
            float v0 = __shfl_sync(FULLM, x2, srcB), v1 = __shfl_sync(FULLM, x3, srcB);
            c[nt][0] = tf32r(odd ? e1 : e0);
            c[nt][1] = tf32r(odd ? u1 : u0);
            c[nt][2] = tf32r(odd ? f1 : f0);
            c[nt][3] = tf32r(odd ? v1 : v0);
        }

        // ================= PV consume: chunk base+4+kg ========================
        const int nv = base + 4 + kg;
        const int qv5 = nv / 5, sv = nv - qv5 * 5;
        MB_WAIT(mb_full + sv * 8, qv5 & 1);
        const float* vb = smf + SLOTS_OFF + sv * SLOT_FLOATS;

        #pragma unroll 2
        for (int kc = 0; kc < 8; kc++) {
            const float* vr = vb + (kc * 8 + t) * 128;
            uint32_t A0 = __float_as_uint(c[kc][0]);
            uint32_t A1 = __float_as_uint(c[kc][1]);
            uint32_t A2 = __float_as_uint(c[kc][2]);
            uint32_t A3 = __float_as_uint(c[kc][3]);
            #pragma unroll
            for (int dt = 0; dt < 16; dt++) {
                const int off0 = ((dt ^ t) << 3) + g24 + g3;
                const int off1 = (off0 ^ 4) + 512;
                mma8(oacc[dt], A0, A1, A2, A3,
                     __float_as_uint(vr[off0]), __float_as_uint(vr[off1]));
            }
        }
        MB_ARRIVE(mb_empty + sv * 8);

        // stage remaining next-jb chunks: K1..K3, V0'
        produce(base + 9); produce(base + 10); produce(base + 11); produce(base + 12);
    }

    // ================= combine 4 kg partials, write O =========================
    __syncthreads();   // all consumption done; safe to reuse smem
    float* obuf = smf;
    if (kg != 0) {
        float* p0 = obuf + ((kg - 1) * 64 + row0) * OSTR + 2 * t;
        float* p1 = p0 + 8 * OSTR;
        #pragma unroll
        for (int dt = 0; dt < 16; dt++) {
            *(float2*)(p0 + dt * 8) = make_float2(oacc[dt][0], oacc[dt][1]);
            *(float2*)(p1 + dt * 8) = make_float2(oacc[dt][2], oacc[dt][3]);
        }
    }
    __syncthreads();
    if (kg == 0) {
        float* o0 = Ob + (size_t)row0 * D_DIM + 2 * t;
        float* o1 = o0 + 8 * D_DIM;
        const float* p0 = obuf + row0 * OSTR + 2 * t;
        const float* p1 = p0 + 8 * OSTR;
        #pragma unroll
        for (int dt = 0; dt < 16; dt++) {
            float a0 = oacc[dt][0], a1 = oacc[dt][1];
            float a2 = oacc[dt][2], a3 = oacc[dt][3];
            #pragma unroll
            for (int j = 0; j < 3; j++) {
                float2 q0 = *(const float2*)(p0 + j * 64 * OSTR + dt * 8);
                float2 q1 = *(const float2*)(p1 + j * 64 * OSTR + dt * 8);
                a0 += q0.x; a1 += q0.y; a2 += q1.x; a3 += q1.y;
            }
            *(float2*)(o0 + dt * 8) = make_float2(a0, a1);
            *(float2*)(o1 + dt * 8) = make_float2(a2, a3);
        }
    }
}

// ---------------------------------------------------------------------------
extern "C" void kernel_launch(void* const* d_in, const int* in_sizes, int n_in,
                              void* d_out, int out_size) {
    const float* Q = (const float*)d_in[0];
    const float* K = (const float*)d_in[1];
    const float* V = (const float*)d_in[2];
    float* O = (float*)d_out;

    const int bh = in_sizes[0] / (S_LEN * D_DIM);   // 32

    round_kernel<<<dim3((unsigned)((size_t)bh * S_LEN * D_DIM / 4 / 256), 2), 256>>>(K, V);

    const size_t smem_bytes = (size_t)SMEM_FLOATS * sizeof(float);
    cudaFuncSetAttribute(attn_mma_kernel, cudaFuncAttributeMaxDynamicSharedMemorySize,
                         (int)smem_bytes);
    attn_mma_kernel<<<dim3(S_LEN / 64, bh), NT, smem_bytes>>>(Q, O);
}